// round 3
// baseline (speedup 1.0000x reference)
#include <cuda_runtime.h>
#include <cuda_bf16.h>
#include <cstdint>

// ---------------------------------------------------------------------------
// GCNEncoder: two layers of  relu(BN(GCN_conv(x)))
//   gcn_conv: h = x@W ; out[dst] += h[src]*dinv[src]*dinv[dst] (incl self loops) ; +b
//   BN: per-column mean/biased-var normalize, scale by gamma, shift by beta
// N=50000, E=800000, C=H=128
// ---------------------------------------------------------------------------

#define HDIM 128
#define MAXN 65536
#define MAXE 1200000

// Scratch (allocation-free rule: __device__ globals)
__device__ __align__(128) float g_h[(size_t)MAXN * HDIM];     // dense transform result
__device__ __align__(128) float g_agg[(size_t)MAXN * HDIM];   // aggregation buffer
__device__ __align__(128) float g_x1[(size_t)MAXN * HDIM];    // layer-1 output
__device__ __align__(128) int   g_src[MAXE];
__device__ __align__(128) int   g_dst[MAXE];
__device__ __align__(128) float g_norm[MAXE];
__device__ __align__(128) float g_dinv[MAXN];                 // deg then rsqrt(deg)
__device__ __align__(128) float g_stats[2 * HDIM];            // colsum, colsumsq
__device__ __align__(128) float g_scale[HDIM];
__device__ __align__(128) float g_shift[HDIM];
__device__ int g_is64;

// ---------------------------------------------------------------------------
__device__ __forceinline__ void red_add_v4(float* addr, float4 v) {
    asm volatile("red.global.add.v4.f32 [%0], {%1,%2,%3,%4};"
                 :: "l"(addr), "f"(v.x), "f"(v.y), "f"(v.z), "f"(v.w)
                 : "memory");
}

// --- dtype sniffer: int64 edge_index has zero upper words -------------------
__global__ void k_detect(const unsigned int* __restrict__ w, int E) {
    int ok = 1;
    int lim = 64;
    for (int i = 0; i < lim; i++) {
        if (2 * i + 1 >= 2 * E) break;
        if (w[2 * i + 1] != 0u) { ok = 0; break; }
    }
    g_is64 = ok;
}

__global__ void k_convert(const void* __restrict__ ei, int E) {
    int i = blockIdx.x * blockDim.x + threadIdx.x;
    if (i >= E) return;
    if (g_is64) {
        const long long* p = (const long long*)ei;
        g_src[i] = (int)p[i];
        g_dst[i] = (int)p[(size_t)E + i];
    } else {
        const int* p = (const int*)ei;
        g_src[i] = p[i];
        g_dst[i] = p[E + i];
    }
}

// --- degree / norm -----------------------------------------------------------
__global__ void k_initdeg(int n) {
    int i = blockIdx.x * blockDim.x + threadIdx.x;
    if (i < n) g_dinv[i] = 1.0f;  // self-loop
}
__global__ void k_degcount(int E) {
    int i = blockIdx.x * blockDim.x + threadIdx.x;
    if (i < E) atomicAdd(&g_dinv[g_dst[i]], 1.0f);
}
__global__ void k_dinv(int n) {
    int i = blockIdx.x * blockDim.x + threadIdx.x;
    if (i < n) g_dinv[i] = rsqrtf(g_dinv[i]);
}
__global__ void k_norm(int E) {
    int i = blockIdx.x * blockDim.x + threadIdx.x;
    if (i < E) g_norm[i] = g_dinv[g_src[i]] * g_dinv[g_dst[i]];
}

// --- SGEMM 128x128x8 tiles, fused self-loop + bias epilogue ------------------
// C = A[M,128] @ W[128,128];  H <- C ;  AGG <- C * dinv[row]^2 + bias
__global__ void __launch_bounds__(256)
k_gemm(const float* __restrict__ A, const float* __restrict__ W,
       const float* __restrict__ bias,
       float* __restrict__ Hout, float* __restrict__ AGG, int M) {
    __shared__ float As[8][128];
    __shared__ float Bs[8][128];
    const int tid = threadIdx.x;
    const int tx = tid & 15;        // 0..15 -> 8 cols each
    const int ty = tid >> 4;        // 0..15 -> 8 rows each
    const int rowBase = blockIdx.x * 128;

    float acc[8][8];
#pragma unroll
    for (int i = 0; i < 8; i++)
#pragma unroll
        for (int j = 0; j < 8; j++) acc[i][j] = 0.f;

    const int aRow = tid >> 1;           // 0..127
    const int aK   = (tid & 1) * 4;      // 0 or 4
    const int bK   = tid >> 5;           // 0..7
    const int bCol = (tid & 31) * 4;

    for (int k0 = 0; k0 < 128; k0 += 8) {
        float4 av = make_float4(0.f, 0.f, 0.f, 0.f);
        int gr = rowBase + aRow;
        if (gr < M) av = *(const float4*)(A + (size_t)gr * 128 + k0 + aK);
        As[aK + 0][aRow] = av.x;
        As[aK + 1][aRow] = av.y;
        As[aK + 2][aRow] = av.z;
        As[aK + 3][aRow] = av.w;
        float4 bv = *(const float4*)(W + (size_t)(k0 + bK) * 128 + bCol);
        *(float4*)&Bs[bK][bCol] = bv;
        __syncthreads();
#pragma unroll
        for (int k = 0; k < 8; k++) {
            float4 ra0 = *(const float4*)&As[k][ty * 8];
            float4 ra1 = *(const float4*)&As[k][ty * 8 + 4];
            float4 rb0 = *(const float4*)&Bs[k][tx * 8];
            float4 rb1 = *(const float4*)&Bs[k][tx * 8 + 4];
            float ra[8] = {ra0.x, ra0.y, ra0.z, ra0.w, ra1.x, ra1.y, ra1.z, ra1.w};
            float rb[8] = {rb0.x, rb0.y, rb0.z, rb0.w, rb1.x, rb1.y, rb1.z, rb1.w};
#pragma unroll
            for (int i = 0; i < 8; i++)
#pragma unroll
                for (int j = 0; j < 8; j++) acc[i][j] = fmaf(ra[i], rb[j], acc[i][j]);
        }
        __syncthreads();
    }

    float bv[8];
#pragma unroll
    for (int j = 0; j < 8; j++) bv[j] = bias[tx * 8 + j];

#pragma unroll
    for (int i = 0; i < 8; i++) {
        int gr = rowBase + ty * 8 + i;
        if (gr < M) {
            float di = g_dinv[gr];
            float w2 = di * di;  // self-loop norm = 1/deg
            size_t off = (size_t)gr * 128 + tx * 8;
            float4 h0 = make_float4(acc[i][0], acc[i][1], acc[i][2], acc[i][3]);
            float4 h1 = make_float4(acc[i][4], acc[i][5], acc[i][6], acc[i][7]);
            *(float4*)(Hout + off)     = h0;
            *(float4*)(Hout + off + 4) = h1;
            float4 a0 = make_float4(fmaf(h0.x, w2, bv[0]), fmaf(h0.y, w2, bv[1]),
                                    fmaf(h0.z, w2, bv[2]), fmaf(h0.w, w2, bv[3]));
            float4 a1 = make_float4(fmaf(h1.x, w2, bv[4]), fmaf(h1.y, w2, bv[5]),
                                    fmaf(h1.z, w2, bv[6]), fmaf(h1.w, w2, bv[7]));
            *(float4*)(AGG + off)     = a0;
            *(float4*)(AGG + off + 4) = a1;
        }
    }
}

// --- edge scatter: one warp per edge, vector atomics -------------------------
__global__ void __launch_bounds__(256)
k_scatter(const float* __restrict__ h, float* __restrict__ agg, int E) {
    int gw = (blockIdx.x * blockDim.x + threadIdx.x) >> 5;
    if (gw >= E) return;
    int lane = threadIdx.x & 31;
    int s = g_src[gw];
    int d = g_dst[gw];
    float nm = g_norm[gw];
    float4 v = __ldg((const float4*)(h + (size_t)s * 128) + lane);
    v.x *= nm; v.y *= nm; v.z *= nm; v.w *= nm;
    red_add_v4(agg + (size_t)d * 128 + (size_t)lane * 4, v);
}

// --- BN ----------------------------------------------------------------------
__global__ void k_statzero() {
    if (threadIdx.x < 2 * HDIM) g_stats[threadIdx.x] = 0.f;
}

__global__ void __launch_bounds__(256)
k_stats(const float* __restrict__ a, int n) {
    __shared__ float ssum[HDIM];
    __shared__ float ssq[HDIM];
    int lane = threadIdx.x & 31;
    int warp = threadIdx.x >> 5;   // 8 warps
    int cb = lane * 4;
    float4 s = make_float4(0.f, 0.f, 0.f, 0.f);
    float4 q = make_float4(0.f, 0.f, 0.f, 0.f);
    for (int r = blockIdx.x * 8 + warp; r < n; r += gridDim.x * 8) {
        float4 v = __ldg((const float4*)(a + (size_t)r * 128 + cb));
        s.x += v.x; s.y += v.y; s.z += v.z; s.w += v.w;
        q.x += v.x * v.x; q.y += v.y * v.y; q.z += v.z * v.z; q.w += v.w * v.w;
    }
    if (threadIdx.x < HDIM) { ssum[threadIdx.x] = 0.f; ssq[threadIdx.x] = 0.f; }
    __syncthreads();
    atomicAdd(&ssum[cb + 0], s.x); atomicAdd(&ssum[cb + 1], s.y);
    atomicAdd(&ssum[cb + 2], s.z); atomicAdd(&ssum[cb + 3], s.w);
    atomicAdd(&ssq[cb + 0], q.x);  atomicAdd(&ssq[cb + 1], q.y);
    atomicAdd(&ssq[cb + 2], q.z);  atomicAdd(&ssq[cb + 3], q.w);
    __syncthreads();
    if (threadIdx.x < HDIM) {
        atomicAdd(&g_stats[threadIdx.x], ssum[threadIdx.x]);
        atomicAdd(&g_stats[HDIM + threadIdx.x], ssq[threadIdx.x]);
    }
}

__global__ void k_bnfinal(const float* __restrict__ gamma,
                          const float* __restrict__ beta, int n) {
    int c = threadIdx.x;
    if (c >= HDIM) return;
    float invn = 1.0f / (float)n;
    float mu = g_stats[c] * invn;
    float var = g_stats[HDIM + c] * invn - mu * mu;
    float inv = rsqrtf(var + 1e-5f);
    float sc = gamma[c] * inv;
    g_scale[c] = sc;
    g_shift[c] = beta[c] - mu * sc;
}

__global__ void __launch_bounds__(256)
k_bnapply(const float* __restrict__ a, float* __restrict__ y, int n) {
    int idx = blockIdx.x * blockDim.x + threadIdx.x;      // float4 index
    int total = n * (HDIM / 4);
    if (idx >= total) return;
    int c4 = (idx & 31) * 4;
    float4 v = __ldg((const float4*)a + idx);
    float4 sc = *(const float4*)&g_scale[c4];
    float4 sh = *(const float4*)&g_shift[c4];
    float4 o;
    o.x = fmaxf(0.f, fmaf(v.x, sc.x, sh.x));
    o.y = fmaxf(0.f, fmaf(v.y, sc.y, sh.y));
    o.z = fmaxf(0.f, fmaf(v.z, sc.z, sh.z));
    o.w = fmaxf(0.f, fmaf(v.w, sc.w, sh.w));
    ((float4*)y)[idx] = o;
}

// ---------------------------------------------------------------------------
static void run_layer(const float* X, const float* W, const float* b,
                      const float* gamma, const float* beta,
                      float* Y, int n, int E) {
    float* h = nullptr;
    float* agg = nullptr;
    cudaGetSymbolAddress((void**)&h, g_h);
    cudaGetSymbolAddress((void**)&agg, g_agg);

    int gemmBlocks = (n + 127) / 128;
    k_gemm<<<gemmBlocks, 256>>>(X, W, b, h, agg, n);

    int scatBlocks = (E + 7) / 8;  // 8 warps per block, warp per edge
    k_scatter<<<scatBlocks, 256>>>(h, agg, E);

    k_statzero<<<1, 256>>>();
    k_stats<<<296, 256>>>(agg, n);
    k_bnfinal<<<1, 128>>>(gamma, beta, n);

    int apBlocks = (n * (HDIM / 4) + 255) / 256;
    k_bnapply<<<apBlocks, 256>>>(agg, Y, n);
}

extern "C" void kernel_launch(void* const* d_in, const int* in_sizes, int n_in,
                              void* d_out, int out_size) {
    const float* x0  = (const float*)d_in[0];
    const void*  ei  = d_in[1];
    const float* W1  = (const float*)d_in[2];
    const float* b1  = (const float*)d_in[3];
    const float* W2  = (const float*)d_in[4];
    const float* b2  = (const float*)d_in[5];
    const float* g1  = (const float*)d_in[6];
    const float* be1 = (const float*)d_in[7];
    const float* g2  = (const float*)d_in[8];
    const float* be2 = (const float*)d_in[9];

    int n = in_sizes[0] / HDIM;
    int E = in_sizes[1] / 2;

    float* x1 = nullptr;
    cudaGetSymbolAddress((void**)&x1, g_x1);

    // --- edge preprocessing (shared by both layers) ---
    k_detect<<<1, 1>>>((const unsigned int*)ei, E);
    k_convert<<<(E + 255) / 256, 256>>>(ei, E);
    k_initdeg<<<(n + 255) / 256, 256>>>(n);
    k_degcount<<<(E + 255) / 256, 256>>>(E);
    k_dinv<<<(n + 255) / 256, 256>>>(n);
    k_norm<<<(E + 255) / 256, 256>>>(E);

    // --- layer 1: x0 -> x1 ---
    run_layer(x0, W1, b1, g1, be1, x1, n, E);
    // --- layer 2: x1 -> out ---
    run_layer(x1, W2, b2, g2, be2, (float*)d_out, n, E);
}

// round 5
// speedup vs baseline: 1.1599x; 1.1599x over previous
#include <cuda_runtime.h>
#include <cuda_bf16.h>
#include <cstdint>

// ---------------------------------------------------------------------------
// GCNEncoder: two layers of relu(BN(GCN_conv(x)))
// CSR-gather aggregation (no global atomics in hot path), BN fused.
// N=50000, E=800000, C=H=128
// ---------------------------------------------------------------------------

#define HDIM 128
#define MAXN 65536
#define MAXE 1200000

__device__ __align__(128) float g_h[(size_t)MAXN * HDIM];     // dense transform result
__device__ __align__(128) float g_agg[(size_t)MAXN * HDIM];   // aggregation buffer
__device__ __align__(128) int   g_src[MAXE];
__device__ __align__(128) int   g_dst[MAXE];
__device__ __align__(128) int   g_adj[MAXE];                  // CSR column indices (src)
__device__ __align__(128) int   g_off[MAXN + 1];              // CSR row offsets (by dst)
__device__ __align__(128) int   g_deg[MAXN];
__device__ __align__(128) int   g_cursor[MAXN];
__device__ __align__(128) float g_dinv[MAXN];                 // rsqrt(deg+1)
__device__ __align__(128) float g_stats[2 * HDIM];            // colsum, colsumsq
__device__ __align__(128) float g_scale[HDIM];
__device__ __align__(128) float g_shift[HDIM];
__device__ int g_is64;

// --- init: zero deg / cursor / stats ----------------------------------------
__global__ void k_init(int n) {
    int i = blockIdx.x * blockDim.x + threadIdx.x;
    if (i < n) { g_deg[i] = 0; g_cursor[i] = 0; }
    if (i < 2 * HDIM) g_stats[i] = 0.f;
}

// --- dtype sniffer: int64 edge_index has zero upper words -------------------
__global__ void k_detect(const unsigned int* __restrict__ w, int E) {
    int ok = 1;
    for (int i = 0; i < 64; i++) {
        if (2 * i + 1 >= 2 * E) break;
        if (w[2 * i + 1] != 0u) { ok = 0; break; }
    }
    g_is64 = ok;
}

// --- convert to int32 + degree count ----------------------------------------
__global__ void k_convert(const void* __restrict__ ei, int E) {
    int i = blockIdx.x * blockDim.x + threadIdx.x;
    if (i >= E) return;
    int s, d;
    if (g_is64) {
        const long long* p = (const long long*)ei;
        s = (int)p[i];
        d = (int)p[(size_t)E + i];
    } else {
        const int* p = (const int*)ei;
        s = p[i];
        d = p[E + i];
    }
    g_src[i] = s;
    g_dst[i] = d;
    atomicAdd(&g_deg[d], 1);
}

// --- single-block exclusive scan of degrees -> offsets, plus dinv ------------
__global__ void __launch_bounds__(1024)
k_scan(int n, int E) {
    __shared__ int tsum[1024];
    int tid = threadIdx.x;
    int per = (n + 1023) / 1024;
    int s = tid * per;
    int e = min(s + per, n);
    int loc = 0;
    for (int i = s; i < e; i++) loc += g_deg[i];
    tsum[tid] = loc;
    __syncthreads();
    // Hillis-Steele inclusive scan
    for (int d = 1; d < 1024; d <<= 1) {
        int v = tsum[tid];
        int u = (tid >= d) ? tsum[tid - d] : 0;
        __syncthreads();
        tsum[tid] = v + u;
        __syncthreads();
    }
    int run = (tid == 0) ? 0 : tsum[tid - 1];
    for (int i = s; i < e; i++) {
        g_off[i] = run;
        run += g_deg[i];
        g_dinv[i] = rsqrtf((float)(g_deg[i] + 1));  // +1 self-loop
    }
    if (tid == 0) g_off[n] = E;
}

// --- CSR fill ----------------------------------------------------------------
__global__ void k_fill(int E) {
    int i = blockIdx.x * blockDim.x + threadIdx.x;
    if (i >= E) return;
    int d = g_dst[i];
    int pos = atomicAdd(&g_cursor[d], 1);
    g_adj[g_off[d] + pos] = g_src[i];
}

// --- SGEMM 128x128x8 tiles. Optional fused BN+ReLU on A load -----------------
// H <- relu(BN(A)) @ W   (BN applied iff BN template flag)
template <bool BN>
__global__ void __launch_bounds__(256)
k_gemm(const float* __restrict__ A, const float* __restrict__ W,
       float* __restrict__ Hout, int M) {
    __shared__ float As[8][128];
    __shared__ float Bs[8][128];
    const int tid = threadIdx.x;
    const int tx = tid & 15;        // 0..15 -> 8 cols each
    const int ty = tid >> 4;        // 0..15 -> 8 rows each
    const int rowBase = blockIdx.x * 128;

    float acc[8][8];
#pragma unroll
    for (int i = 0; i < 8; i++)
#pragma unroll
        for (int j = 0; j < 8; j++) acc[i][j] = 0.f;

    const int aRow = tid >> 1;           // 0..127
    const int aK   = (tid & 1) * 4;      // 0 or 4
    const int bK   = tid >> 5;           // 0..7
    const int bCol = (tid & 31) * 4;

    for (int k0 = 0; k0 < 128; k0 += 8) {
        float4 av = make_float4(0.f, 0.f, 0.f, 0.f);
        int gr = rowBase + aRow;
        if (gr < M) {
            av = *(const float4*)(A + (size_t)gr * 128 + k0 + aK);
            if (BN) {
                float4 sc = *(const float4*)&g_scale[k0 + aK];
                float4 sh = *(const float4*)&g_shift[k0 + aK];
                av.x = fmaxf(0.f, fmaf(av.x, sc.x, sh.x));
                av.y = fmaxf(0.f, fmaf(av.y, sc.y, sh.y));
                av.z = fmaxf(0.f, fmaf(av.z, sc.z, sh.z));
                av.w = fmaxf(0.f, fmaf(av.w, sc.w, sh.w));
            }
        }
        As[aK + 0][aRow] = av.x;
        As[aK + 1][aRow] = av.y;
        As[aK + 2][aRow] = av.z;
        As[aK + 3][aRow] = av.w;
        float4 bv = *(const float4*)(W + (size_t)(k0 + bK) * 128 + bCol);
        *(float4*)&Bs[bK][bCol] = bv;
        __syncthreads();
#pragma unroll
        for (int k = 0; k < 8; k++) {
            float4 ra0 = *(const float4*)&As[k][ty * 8];
            float4 ra1 = *(const float4*)&As[k][ty * 8 + 4];
            float4 rb0 = *(const float4*)&Bs[k][tx * 8];
            float4 rb1 = *(const float4*)&Bs[k][tx * 8 + 4];
            float ra[8] = {ra0.x, ra0.y, ra0.z, ra0.w, ra1.x, ra1.y, ra1.z, ra1.w};
            float rb[8] = {rb0.x, rb0.y, rb0.z, rb0.w, rb1.x, rb1.y, rb1.z, rb1.w};
#pragma unroll
            for (int i = 0; i < 8; i++)
#pragma unroll
                for (int j = 0; j < 8; j++) acc[i][j] = fmaf(ra[i], rb[j], acc[i][j]);
        }
        __syncthreads();
    }

#pragma unroll
    for (int i = 0; i < 8; i++) {
        int gr = rowBase + ty * 8 + i;
        if (gr < M) {
            size_t off = (size_t)gr * 128 + tx * 8;
            *(float4*)(Hout + off)     = make_float4(acc[i][0], acc[i][1], acc[i][2], acc[i][3]);
            *(float4*)(Hout + off + 4) = make_float4(acc[i][4], acc[i][5], acc[i][6], acc[i][7]);
        }
    }
}

// --- CSR gather aggregation + self loop + bias + fused BN stats --------------
// out[v] = dinv[v] * sum_e dinv[src_e]*h[src_e]  +  dinv[v]^2 * h[v]  + bias
__global__ void __launch_bounds__(256)
k_aggregate(const float* __restrict__ h, const float* __restrict__ bias,
            float* __restrict__ out, int n) {
    __shared__ float s_sum[HDIM];
    __shared__ float s_sq[HDIM];
    const int lane = threadIdx.x & 31;
    const int warp = threadIdx.x >> 5;
    const int gw = blockIdx.x * 8 + warp;
    const int nw = gridDim.x * 8;

    if (threadIdx.x < HDIM) { s_sum[threadIdx.x] = 0.f; s_sq[threadIdx.x] = 0.f; }
    __syncthreads();

    float4 bv = ((const float4*)bias)[lane];
    float4 csum = make_float4(0.f, 0.f, 0.f, 0.f);
    float4 csq  = make_float4(0.f, 0.f, 0.f, 0.f);

    for (int v = gw; v < n; v += nw) {
        int beg = g_off[v], end = g_off[v + 1];
        float4 acc = make_float4(0.f, 0.f, 0.f, 0.f);
        int e = beg;
        for (; e + 4 <= end; e += 4) {
            int s0 = g_adj[e], s1 = g_adj[e + 1], s2 = g_adj[e + 2], s3 = g_adj[e + 3];
            float w0 = g_dinv[s0], w1 = g_dinv[s1], w2 = g_dinv[s2], w3 = g_dinv[s3];
            float4 v0 = __ldg((const float4*)(h + (size_t)s0 * 128) + lane);
            float4 v1 = __ldg((const float4*)(h + (size_t)s1 * 128) + lane);
            float4 v2 = __ldg((const float4*)(h + (size_t)s2 * 128) + lane);
            float4 v3 = __ldg((const float4*)(h + (size_t)s3 * 128) + lane);
            acc.x += w0 * v0.x + w1 * v1.x + w2 * v2.x + w3 * v3.x;
            acc.y += w0 * v0.y + w1 * v1.y + w2 * v2.y + w3 * v3.y;
            acc.z += w0 * v0.z + w1 * v1.z + w2 * v2.z + w3 * v3.z;
            acc.w += w0 * v0.w + w1 * v1.w + w2 * v2.w + w3 * v3.w;
        }
        for (; e < end; e++) {
            int s0 = g_adj[e];
            float w0 = g_dinv[s0];
            float4 v0 = __ldg((const float4*)(h + (size_t)s0 * 128) + lane);
            acc.x += w0 * v0.x; acc.y += w0 * v0.y;
            acc.z += w0 * v0.z; acc.w += w0 * v0.w;
        }
        float dv = g_dinv[v];
        float dv2 = dv * dv;
        float4 hv = __ldg((const float4*)(h + (size_t)v * 128) + lane);
        float4 o;
        o.x = fmaf(dv, acc.x, fmaf(dv2, hv.x, bv.x));
        o.y = fmaf(dv, acc.y, fmaf(dv2, hv.y, bv.y));
        o.z = fmaf(dv, acc.z, fmaf(dv2, hv.z, bv.z));
        o.w = fmaf(dv, acc.w, fmaf(dv2, hv.w, bv.w));
        ((float4*)(out + (size_t)v * 128))[lane] = o;
        csum.x += o.x; csum.y += o.y; csum.z += o.z; csum.w += o.w;
        csq.x += o.x * o.x; csq.y += o.y * o.y;
        csq.z += o.z * o.z; csq.w += o.w * o.w;
    }

    // block-level BN stats reduction
    int cb = lane * 4;
    atomicAdd(&s_sum[cb + 0], csum.x); atomicAdd(&s_sum[cb + 1], csum.y);
    atomicAdd(&s_sum[cb + 2], csum.z); atomicAdd(&s_sum[cb + 3], csum.w);
    atomicAdd(&s_sq[cb + 0], csq.x);   atomicAdd(&s_sq[cb + 1], csq.y);
    atomicAdd(&s_sq[cb + 2], csq.z);   atomicAdd(&s_sq[cb + 3], csq.w);
    __syncthreads();
    if (threadIdx.x < HDIM) {
        atomicAdd(&g_stats[threadIdx.x], s_sum[threadIdx.x]);
        atomicAdd(&g_stats[HDIM + threadIdx.x], s_sq[threadIdx.x]);
    }
}

// --- BN finalize: scale/shift from stats; resets stats for next layer --------
__global__ void k_bnfinal(const float* __restrict__ gamma,
                          const float* __restrict__ beta, int n) {
    int c = threadIdx.x;
    if (c >= HDIM) return;
    float invn = 1.0f / (float)n;
    float mu = g_stats[c] * invn;
    float var = g_stats[HDIM + c] * invn - mu * mu;
    float inv = rsqrtf(var + 1e-5f);
    float sc = gamma[c] * inv;
    g_scale[c] = sc;
    g_shift[c] = beta[c] - mu * sc;
    g_stats[c] = 0.f;
    g_stats[HDIM + c] = 0.f;
}

// --- final BN apply + relu (layer-2 output only) ------------------------------
__global__ void __launch_bounds__(256)
k_bnapply(const float* __restrict__ a, float* __restrict__ y, int n) {
    int idx = blockIdx.x * blockDim.x + threadIdx.x;      // float4 index
    int total = n * (HDIM / 4);
    if (idx >= total) return;
    int c4 = (idx & 31) * 4;
    float4 v = __ldg((const float4*)a + idx);
    float4 sc = *(const float4*)&g_scale[c4];
    float4 sh = *(const float4*)&g_shift[c4];
    float4 o;
    o.x = fmaxf(0.f, fmaf(v.x, sc.x, sh.x));
    o.y = fmaxf(0.f, fmaf(v.y, sc.y, sh.y));
    o.z = fmaxf(0.f, fmaf(v.z, sc.z, sh.z));
    o.w = fmaxf(0.f, fmaf(v.w, sc.w, sh.w));
    ((float4*)y)[idx] = o;
}

// ---------------------------------------------------------------------------
extern "C" void kernel_launch(void* const* d_in, const int* in_sizes, int n_in,
                              void* d_out, int out_size) {
    const float* x0  = (const float*)d_in[0];
    const void*  ei  = d_in[1];
    const float* W1  = (const float*)d_in[2];
    const float* b1  = (const float*)d_in[3];
    const float* W2  = (const float*)d_in[4];
    const float* b2  = (const float*)d_in[5];
    const float* g1  = (const float*)d_in[6];
    const float* be1 = (const float*)d_in[7];
    const float* g2  = (const float*)d_in[8];
    const float* be2 = (const float*)d_in[9];

    int n = in_sizes[0] / HDIM;
    int E = in_sizes[1] / 2;

    float* h = nullptr;
    float* agg = nullptr;
    cudaGetSymbolAddress((void**)&h, g_h);
    cudaGetSymbolAddress((void**)&agg, g_agg);

    // --- preprocessing (5 launches; 6th launch = gemm1 for ncu -s 5 -c 1) ---
    k_init<<<(n + 255) / 256, 256>>>(n);
    k_detect<<<1, 1>>>((const unsigned int*)ei, E);
    k_convert<<<(E + 255) / 256, 256>>>(ei, E);
    k_scan<<<1, 1024>>>(n, E);
    k_fill<<<(E + 255) / 256, 256>>>(E);

    int gemmBlocks = (n + 127) / 128;
    int aggBlocks = 592;  // 4 per SM

    // --- layer 1 ---
    k_gemm<false><<<gemmBlocks, 256>>>(x0, W1, h, n);
    k_aggregate<<<aggBlocks, 256>>>(h, b1, agg, n);
    k_bnfinal<<<1, 128>>>(g1, be1, n);

    // --- layer 2 (BN1+relu fused into A load) ---
    k_gemm<true><<<gemmBlocks, 256>>>(agg, W2, h, n);
    k_aggregate<<<aggBlocks, 256>>>(h, b2, agg, n);
    k_bnfinal<<<1, 128>>>(g2, be2, n);

    int apBlocks = (n * (HDIM / 4) + 255) / 256;
    k_bnapply<<<apBlocks, 256>>>(agg, (float*)d_out, n);
}

// round 8
// speedup vs baseline: 1.5107x; 1.3025x over previous
#include <cuda_runtime.h>
#include <cuda_bf16.h>
#include <cstdint>

// ---------------------------------------------------------------------------
// GCNEncoder: two layers of relu(BN(GCN_conv(x)))
// CSR-gather aggregation (no global atomics in hot path), BN fused,
// two-level parallel scan for CSR offsets.
// N=50000, E=800000, C=H=128
// ---------------------------------------------------------------------------

#define HDIM 128
#define MAXN 65536
#define MAXE 1200000
#define SCAN_B 256  // elems per scan block

__device__ __align__(128) float g_h[(size_t)MAXN * HDIM];     // dense transform result
__device__ __align__(128) float g_agg[(size_t)MAXN * HDIM];   // aggregation buffer
__device__ __align__(128) int   g_src[MAXE];
__device__ __align__(128) int   g_dst[MAXE];
__device__ __align__(128) int   g_adj[MAXE];                  // CSR column indices (src)
__device__ __align__(128) int   g_off[MAXN + 1];              // CSR row offsets (by dst)
__device__ __align__(128) int   g_deg[MAXN];
__device__ __align__(128) int   g_cursor[MAXN];
__device__ __align__(128) float g_dinv[MAXN];                 // rsqrt(deg+1)
__device__ __align__(128) int   g_bsum[MAXN / SCAN_B + 2];    // per-block sums
__device__ __align__(128) int   g_bbase[MAXN / SCAN_B + 2];   // exclusive block bases
__device__ __align__(128) float g_stats[2 * HDIM];            // colsum, colsumsq
__device__ __align__(128) float g_scale[HDIM];
__device__ __align__(128) float g_shift[HDIM];
__device__ int g_is64;

// --- init: zero deg / stats ---------------------------------------------------
__global__ void k_init(int n) {
    int i = blockIdx.x * blockDim.x + threadIdx.x;
    if (i < n) g_deg[i] = 0;
    if (i < 2 * HDIM) g_stats[i] = 0.f;
}

// --- dtype sniffer: int64 edge_index has zero upper words -------------------
__global__ void k_detect(const unsigned int* __restrict__ w, int E) {
    int ok = 1;
    for (int i = 0; i < 64; i++) {
        if (2 * i + 1 >= 2 * E) break;
        if (w[2 * i + 1] != 0u) { ok = 0; break; }
    }
    g_is64 = ok;
}

// --- convert to int32 + degree count ----------------------------------------
__global__ void k_convert(const void* __restrict__ ei, int E) {
    int i = blockIdx.x * blockDim.x + threadIdx.x;
    if (i >= E) return;
    int s, d;
    if (g_is64) {
        const long long* p = (const long long*)ei;
        s = (int)p[i];
        d = (int)p[(size_t)E + i];
    } else {
        const int* p = (const int*)ei;
        s = p[i];
        d = p[E + i];
    }
    g_src[i] = s;
    g_dst[i] = d;
    atomicAdd(&g_deg[d], 1);
}

// --- two-level scan ----------------------------------------------------------
// A: per-block reduction of degrees
__global__ void __launch_bounds__(SCAN_B)
k_scanA(int n) {
    __shared__ int sh[SCAN_B / 32];
    int i = blockIdx.x * SCAN_B + threadIdx.x;
    int v = (i < n) ? g_deg[i] : 0;
#pragma unroll
    for (int o = 16; o > 0; o >>= 1) v += __shfl_down_sync(0xffffffffu, v, o);
    int lane = threadIdx.x & 31, warp = threadIdx.x >> 5;
    if (lane == 0) sh[warp] = v;
    __syncthreads();
    if (warp == 0) {
        int w = (lane < SCAN_B / 32) ? sh[lane] : 0;
#pragma unroll
        for (int o = 4; o > 0; o >>= 1) w += __shfl_down_sync(0xffffffffu, w, o);
        if (lane == 0) g_bsum[blockIdx.x] = w;
    }
}

// B: single block scans block sums (nb <= 256) -> exclusive bases
__global__ void __launch_bounds__(SCAN_B)
k_scanB(int nb) {
    __shared__ int sh[SCAN_B];
    int tid = threadIdx.x;
    int v = (tid < nb) ? g_bsum[tid] : 0;
    sh[tid] = v;
    __syncthreads();
    for (int d = 1; d < SCAN_B; d <<= 1) {
        int u = (tid >= d) ? sh[tid - d] : 0;
        __syncthreads();
        sh[tid] += u;
        __syncthreads();
    }
    if (tid < nb) g_bbase[tid] = sh[tid] - v;  // exclusive
}

// C: block-local exclusive scan + base -> offsets, cursor copy, dinv
__global__ void __launch_bounds__(SCAN_B)
k_scanC(int n, int E) {
    __shared__ int sh[SCAN_B];
    int tid = threadIdx.x;
    int i = blockIdx.x * SCAN_B + tid;
    int deg = (i < n) ? g_deg[i] : 0;
    sh[tid] = deg;
    __syncthreads();
    for (int d = 1; d < SCAN_B; d <<= 1) {
        int u = (tid >= d) ? sh[tid - d] : 0;
        __syncthreads();
        sh[tid] += u;
        __syncthreads();
    }
    if (i < n) {
        int off = g_bbase[blockIdx.x] + sh[tid] - deg;
        g_off[i] = off;
        g_cursor[i] = off;
        g_dinv[i] = rsqrtf((float)(deg + 1));  // +1 self-loop
    }
    if (i == 0) g_off[n] = E;
}

// --- CSR fill (cursor pre-seeded with offsets) --------------------------------
__global__ void k_fill(int E) {
    int i = blockIdx.x * blockDim.x + threadIdx.x;
    if (i >= E) return;
    int pos = atomicAdd(&g_cursor[g_dst[i]], 1);
    g_adj[pos] = g_src[i];
}

// --- SGEMM 128x128x8 tiles. Optional fused BN+ReLU on A load -----------------
template <bool BN>
__global__ void __launch_bounds__(256)
k_gemm(const float* __restrict__ A, const float* __restrict__ W,
       float* __restrict__ Hout, int M) {
    __shared__ float As[8][128];
    __shared__ float Bs[8][128];
    const int tid = threadIdx.x;
    const int tx = tid & 15;        // 0..15 -> 8 cols each
    const int ty = tid >> 4;        // 0..15 -> 8 rows each
    const int rowBase = blockIdx.x * 128;

    float acc[8][8];
#pragma unroll
    for (int i = 0; i < 8; i++)
#pragma unroll
        for (int j = 0; j < 8; j++) acc[i][j] = 0.f;

    const int aRow = tid >> 1;           // 0..127
    const int aK   = (tid & 1) * 4;      // 0 or 4
    const int bK   = tid >> 5;           // 0..7
    const int bCol = (tid & 31) * 4;

    for (int k0 = 0; k0 < 128; k0 += 8) {
        float4 av = make_float4(0.f, 0.f, 0.f, 0.f);
        int gr = rowBase + aRow;
        if (gr < M) {
            av = *(const float4*)(A + (size_t)gr * 128 + k0 + aK);
            if (BN) {
                float4 sc = *(const float4*)&g_scale[k0 + aK];
                float4 sh = *(const float4*)&g_shift[k0 + aK];
                av.x = fmaxf(0.f, fmaf(av.x, sc.x, sh.x));
                av.y = fmaxf(0.f, fmaf(av.y, sc.y, sh.y));
                av.z = fmaxf(0.f, fmaf(av.z, sc.z, sh.z));
                av.w = fmaxf(0.f, fmaf(av.w, sc.w, sh.w));
            }
        }
        As[aK + 0][aRow] = av.x;
        As[aK + 1][aRow] = av.y;
        As[aK + 2][aRow] = av.z;
        As[aK + 3][aRow] = av.w;
        float4 bv = *(const float4*)(W + (size_t)(k0 + bK) * 128 + bCol);
        *(float4*)&Bs[bK][bCol] = bv;
        __syncthreads();
#pragma unroll
        for (int k = 0; k < 8; k++) {
            float4 ra0 = *(const float4*)&As[k][ty * 8];
            float4 ra1 = *(const float4*)&As[k][ty * 8 + 4];
            float4 rb0 = *(const float4*)&Bs[k][tx * 8];
            float4 rb1 = *(const float4*)&Bs[k][tx * 8 + 4];
            float ra[8] = {ra0.x, ra0.y, ra0.z, ra0.w, ra1.x, ra1.y, ra1.z, ra1.w};
            float rb[8] = {rb0.x, rb0.y, rb0.z, rb0.w, rb1.x, rb1.y, rb1.z, rb1.w};
#pragma unroll
            for (int i = 0; i < 8; i++)
#pragma unroll
                for (int j = 0; j < 8; j++) acc[i][j] = fmaf(ra[i], rb[j], acc[i][j]);
        }
        __syncthreads();
    }

#pragma unroll
    for (int i = 0; i < 8; i++) {
        int gr = rowBase + ty * 8 + i;
        if (gr < M) {
            size_t off = (size_t)gr * 128 + tx * 8;
            *(float4*)(Hout + off)     = make_float4(acc[i][0], acc[i][1], acc[i][2], acc[i][3]);
            *(float4*)(Hout + off + 4) = make_float4(acc[i][4], acc[i][5], acc[i][6], acc[i][7]);
        }
    }
}

// --- CSR gather aggregation + self loop + bias + fused BN stats --------------
__global__ void __launch_bounds__(256)
k_aggregate(const float* __restrict__ h, const float* __restrict__ bias,
            float* __restrict__ out, int n) {
    __shared__ float s_sum[HDIM];
    __shared__ float s_sq[HDIM];
    const int lane = threadIdx.x & 31;
    const int warp = threadIdx.x >> 5;
    const int gw = blockIdx.x * 8 + warp;
    const int nw = gridDim.x * 8;

    if (threadIdx.x < HDIM) { s_sum[threadIdx.x] = 0.f; s_sq[threadIdx.x] = 0.f; }
    __syncthreads();

    float4 bv = ((const float4*)bias)[lane];
    float4 csum = make_float4(0.f, 0.f, 0.f, 0.f);
    float4 csq  = make_float4(0.f, 0.f, 0.f, 0.f);

    for (int v = gw; v < n; v += nw) {
        int beg = g_off[v], end = g_off[v + 1];
        float4 acc = make_float4(0.f, 0.f, 0.f, 0.f);
        int e = beg;
        for (; e + 4 <= end; e += 4) {
            int s0 = g_adj[e], s1 = g_adj[e + 1], s2 = g_adj[e + 2], s3 = g_adj[e + 3];
            float w0 = g_dinv[s0], w1 = g_dinv[s1], w2 = g_dinv[s2], w3 = g_dinv[s3];
            float4 v0 = __ldg((const float4*)(h + (size_t)s0 * 128) + lane);
            float4 v1 = __ldg((const float4*)(h + (size_t)s1 * 128) + lane);
            float4 v2 = __ldg((const float4*)(h + (size_t)s2 * 128) + lane);
            float4 v3 = __ldg((const float4*)(h + (size_t)s3 * 128) + lane);
            acc.x += w0 * v0.x + w1 * v1.x + w2 * v2.x + w3 * v3.x;
            acc.y += w0 * v0.y + w1 * v1.y + w2 * v2.y + w3 * v3.y;
            acc.z += w0 * v0.z + w1 * v1.z + w2 * v2.z + w3 * v3.z;
            acc.w += w0 * v0.w + w1 * v1.w + w2 * v2.w + w3 * v3.w;
        }
        for (; e < end; e++) {
            int s0 = g_adj[e];
            float w0 = g_dinv[s0];
            float4 v0 = __ldg((const float4*)(h + (size_t)s0 * 128) + lane);
            acc.x += w0 * v0.x; acc.y += w0 * v0.y;
            acc.z += w0 * v0.z; acc.w += w0 * v0.w;
        }
        float dv = g_dinv[v];
        float dv2 = dv * dv;
        float4 hv = __ldg((const float4*)(h + (size_t)v * 128) + lane);
        float4 o;
        o.x = fmaf(dv, acc.x, fmaf(dv2, hv.x, bv.x));
        o.y = fmaf(dv, acc.y, fmaf(dv2, hv.y, bv.y));
        o.z = fmaf(dv, acc.z, fmaf(dv2, hv.z, bv.z));
        o.w = fmaf(dv, acc.w, fmaf(dv2, hv.w, bv.w));
        ((float4*)(out + (size_t)v * 128))[lane] = o;
        csum.x += o.x; csum.y += o.y; csum.z += o.z; csum.w += o.w;
        csq.x += o.x * o.x; csq.y += o.y * o.y;
        csq.z += o.z * o.z; csq.w += o.w * o.w;
    }

    int cb = lane * 4;
    atomicAdd(&s_sum[cb + 0], csum.x); atomicAdd(&s_sum[cb + 1], csum.y);
    atomicAdd(&s_sum[cb + 2], csum.z); atomicAdd(&s_sum[cb + 3], csum.w);
    atomicAdd(&s_sq[cb + 0], csq.x);   atomicAdd(&s_sq[cb + 1], csq.y);
    atomicAdd(&s_sq[cb + 2], csq.z);   atomicAdd(&s_sq[cb + 3], csq.w);
    __syncthreads();
    if (threadIdx.x < HDIM) {
        atomicAdd(&g_stats[threadIdx.x], s_sum[threadIdx.x]);
        atomicAdd(&g_stats[HDIM + threadIdx.x], s_sq[threadIdx.x]);
    }
}

// --- BN finalize: scale/shift from stats; resets stats for next layer --------
__global__ void k_bnfinal(const float* __restrict__ gamma,
                          const float* __restrict__ beta, int n) {
    int c = threadIdx.x;
    if (c >= HDIM) return;
    float invn = 1.0f / (float)n;
    float mu = g_stats[c] * invn;
    float var = g_stats[HDIM + c] * invn - mu * mu;
    float inv = rsqrtf(var + 1e-5f);
    float sc = gamma[c] * inv;
    g_scale[c] = sc;
    g_shift[c] = beta[c] - mu * sc;
    g_stats[c] = 0.f;
    g_stats[HDIM + c] = 0.f;
}

// --- final BN apply + relu (layer-2 output only) ------------------------------
__global__ void __launch_bounds__(256)
k_bnapply(const float* __restrict__ a, float* __restrict__ y, int n) {
    int idx = blockIdx.x * blockDim.x + threadIdx.x;      // float4 index
    int total = n * (HDIM / 4);
    if (idx >= total) return;
    int c4 = (idx & 31) * 4;
    float4 v = __ldg((const float4*)a + idx);
    float4 sc = *(const float4*)&g_scale[c4];
    float4 sh = *(const float4*)&g_shift[c4];
    float4 o;
    o.x = fmaxf(0.f, fmaf(v.x, sc.x, sh.x));
    o.y = fmaxf(0.f, fmaf(v.y, sc.y, sh.y));
    o.z = fmaxf(0.f, fmaf(v.z, sc.z, sh.z));
    o.w = fmaxf(0.f, fmaf(v.w, sc.w, sh.w));
    ((float4*)y)[idx] = o;
}

// ---------------------------------------------------------------------------
extern "C" void kernel_launch(void* const* d_in, const int* in_sizes, int n_in,
                              void* d_out, int out_size) {
    const float* x0  = (const float*)d_in[0];
    const void*  ei  = d_in[1];
    const float* W1  = (const float*)d_in[2];
    const float* b1  = (const float*)d_in[3];
    const float* W2  = (const float*)d_in[4];
    const float* b2  = (const float*)d_in[5];
    const float* g1  = (const float*)d_in[6];
    const float* be1 = (const float*)d_in[7];
    const float* g2  = (const float*)d_in[8];
    const float* be2 = (const float*)d_in[9];

    int n = in_sizes[0] / HDIM;
    int E = in_sizes[1] / 2;

    float* h = nullptr;
    float* agg = nullptr;
    cudaGetSymbolAddress((void**)&h, g_h);
    cudaGetSymbolAddress((void**)&agg, g_agg);

    int gemmBlocks = (n + 127) / 128;
    int aggBlocks = 592;  // 4 per SM
    int nb = (n + SCAN_B - 1) / SCAN_B;

    // --- preprocessing; gemm1 placed 4th so ncu captures it ---
    k_init<<<(n + 255) / 256, 256>>>(n);
    k_detect<<<1, 1>>>((const unsigned int*)ei, E);
    k_convert<<<(E + 255) / 256, 256>>>(ei, E);

    // layer-1 GEMM (independent of edge preprocessing)
    k_gemm<false><<<gemmBlocks, 256>>>(x0, W1, h, n);

    k_scanA<<<nb, SCAN_B>>>(n);
    k_scanB<<<1, SCAN_B>>>(nb);
    k_scanC<<<nb, SCAN_B>>>(n, E);
    k_fill<<<(E + 255) / 256, 256>>>(E);

    // --- layer 1 aggregation + BN ---
    k_aggregate<<<aggBlocks, 256>>>(h, b1, agg, n);
    k_bnfinal<<<1, 128>>>(g1, be1, n);

    // --- layer 2 (BN1+relu fused into A load) ---
    k_gemm<true><<<gemmBlocks, 256>>>(agg, W2, h, n);
    k_aggregate<<<aggBlocks, 256>>>(h, b2, agg, n);
    k_bnfinal<<<1, 128>>>(g2, be2, n);

    int apBlocks = (n * (HDIM / 4) + 255) / 256;
    k_bnapply<<<apBlocks, 256>>>(agg, (float*)d_out, n);
}